// round 11
// baseline (speedup 1.0000x reference)
#include <cuda_runtime.h>
#include <cuda_fp16.h>
#include <cstdint>

// ---------------------------------------------------------------------------
// PMWA_24842090840472: 3-hop gated graph aggregation
// R11: R9 base (redux.f32 not supported on sm_103 — reverted to shfl)
//      + packed half2 pair-butterfly (5 fewer instrs/iter)
//      + single predicated quad tail
//      + fused fillb+norm launch (overlap atomic fill with normalize).
// ---------------------------------------------------------------------------

#define DIMS 128
#define NMAX 65537
#define CAP 64

__device__ int g_count[NMAX];
__device__ int g_bkt[(size_t)NMAX * CAP];
// fp16 mirrors of h, ping-pong; row = 32 uint2 = 128 halves (dims in order)
__device__ uint2 g_h16[2][(size_t)NMAX * 32];

// ---------------- Threefry-2x32 (JAX key schedule) -------------------------
#define TF_ROUND(x0, x1, r) \
    do { x0 += x1; x1 = ((x1) << (r)) | ((x1) >> (32 - (r))); x1 ^= x0; } while (0)

__host__ __device__ inline void tf2x32(uint32_t k0, uint32_t k1,
                                       uint32_t x0, uint32_t x1,
                                       uint32_t& o0, uint32_t& o1) {
    uint32_t ks0 = k0, ks1 = k1, ks2 = 0x1BD11BDAu ^ k0 ^ k1;
    x0 += ks0; x1 += ks1;
    TF_ROUND(x0, x1, 13); TF_ROUND(x0, x1, 15); TF_ROUND(x0, x1, 26); TF_ROUND(x0, x1, 6);
    x0 += ks1; x1 += ks2 + 1u;
    TF_ROUND(x0, x1, 17); TF_ROUND(x0, x1, 29); TF_ROUND(x0, x1, 16); TF_ROUND(x0, x1, 24);
    x0 += ks2; x1 += ks0 + 2u;
    TF_ROUND(x0, x1, 13); TF_ROUND(x0, x1, 15); TF_ROUND(x0, x1, 26); TF_ROUND(x0, x1, 6);
    x0 += ks0; x1 += ks1 + 3u;
    TF_ROUND(x0, x1, 17); TF_ROUND(x0, x1, 29); TF_ROUND(x0, x1, 16); TF_ROUND(x0, x1, 24);
    x0 += ks1; x1 += ks2 + 4u;
    TF_ROUND(x0, x1, 13); TF_ROUND(x0, x1, 15); TF_ROUND(x0, x1, 26); TF_ROUND(x0, x1, 6);
    x0 += ks2; x1 += ks0 + 5u;
    o0 = x0; o1 = x1;
}

// XLA/Giles float32 erfinv polynomial
__device__ inline float erfinv_xla(float x) {
    float w = -__logf(fmaf(-x, x, 1.0f));
    float p;
    if (w < 5.0f) {
        w -= 2.5f;
        p = 2.81022636e-08f;
        p = fmaf(p, w, 3.43273939e-07f);
        p = fmaf(p, w, -3.5233877e-06f);
        p = fmaf(p, w, -4.39150654e-06f);
        p = fmaf(p, w, 0.00021858087f);
        p = fmaf(p, w, -0.00125372503f);
        p = fmaf(p, w, -0.00417768164f);
        p = fmaf(p, w, 0.246640727f);
        p = fmaf(p, w, 1.50140941f);
    } else {
        w = sqrtf(w) - 3.0f;
        p = -0.000200214257f;
        p = fmaf(p, w, 0.000100950558f);
        p = fmaf(p, w, 0.00134934322f);
        p = fmaf(p, w, -0.00367342844f);
        p = fmaf(p, w, 0.00573950773f);
        p = fmaf(p, w, -0.0076224613f);
        p = fmaf(p, w, 0.00943887047f);
        p = fmaf(p, w, 1.00167406f);
        p = fmaf(p, w, 2.83297682f);
    }
    return p * x;
}

__device__ inline float tf_normal(uint32_t k0, uint32_t k1, uint32_t idx) {
    uint32_t o0, o1;
    tf2x32(k0, k1, 0u, idx, o0, o1);
    uint32_t bits = o0 ^ o1;
    float f = __uint_as_float(0x3f800000u | (bits >> 9)) - 1.0f;
    float u = fmaf(f, 2.0f, -0.99999994f);
    return 1.41421354f * erfinv_xla(u);
}

// ---------------- helpers --------------------------------------------------
#define BFLY32(d)                                       \
    d += __shfl_xor_sync(0xffffffffu, d, 16);           \
    d += __shfl_xor_sync(0xffffffffu, d, 8);            \
    d += __shfl_xor_sync(0xffffffffu, d, 4);            \
    d += __shfl_xor_sync(0xffffffffu, d, 2);            \
    d += __shfl_xor_sync(0xffffffffu, d, 1);

__device__ __forceinline__ float sigm(float d) {
    return 1.0f / (1.0f + __expf(-d));
}

__device__ __forceinline__ uint2 f4_to_h4(float4 a) {
    __half2 p0 = __floats2half2_rn(a.x, a.y);
    __half2 p1 = __floats2half2_rn(a.z, a.w);
    uint2 u;
    u.x = *(uint32_t*)&p0;
    u.y = *(uint32_t*)&p1;
    return u;
}

// partial dot over this lane's 8 dims (uint4 = 4 half2), fp16 products/f32 tail
__device__ __forceinline__ float dot8(uint4 v, __half2 h0, __half2 h1,
                                      __half2 h2, __half2 h3) {
    __half2 p = __hmul2(*(__half2*)&v.x, h0);
    p = __hfma2(*(__half2*)&v.y, h1, p);
    p = __hfma2(*(__half2*)&v.z, h2, p);
    p = __hfma2(*(__half2*)&v.w, h3, p);
    float2 f = __half22float2(p);
    return f.x + f.y;
}

__device__ __forceinline__ void accum8(float* acc, uint4 v, float a) {
    float2 f0 = __half22float2(*(__half2*)&v.x);
    float2 f1 = __half22float2(*(__half2*)&v.y);
    float2 f2 = __half22float2(*(__half2*)&v.z);
    float2 f3 = __half22float2(*(__half2*)&v.w);
    acc[0] = fmaf(a, f0.x, acc[0]);
    acc[1] = fmaf(a, f0.y, acc[1]);
    acc[2] = fmaf(a, f1.x, acc[2]);
    acc[3] = fmaf(a, f1.y, acc[3]);
    acc[4] = fmaf(a, f2.x, acc[4]);
    acc[5] = fmaf(a, f2.y, acc[5]);
    acc[6] = fmaf(a, f3.x, acc[6]);
    acc[7] = fmaf(a, f3.y, acc[7]);
}

// ---------------- CSR zero -------------------------------------------------
__global__ void k_zero(int N) {
    int i = blockIdx.x * blockDim.x + threadIdx.x;
    if (i < N) g_count[i] = 0;
}

// ------- fused: bucket fill (first fillBlocks) | normalize x (rest) --------
__global__ void k_front(const int* __restrict__ src, const int* __restrict__ dst,
                        int E, const float* __restrict__ x,
                        float* __restrict__ out, int N, int fillBlocks) {
    if ((int)blockIdx.x < fillBlocks) {
        int i = (blockIdx.x * blockDim.x + threadIdx.x) * 2;
        if (i + 1 < E) {
            int2 d = *(const int2*)(dst + i);
            int2 s = *(const int2*)(src + i);
            int p0 = atomicAdd(&g_count[d.x], 1);
            if (p0 < CAP) g_bkt[(size_t)d.x * CAP + p0] = s.x;
            int p1 = atomicAdd(&g_count[d.y], 1);
            if (p1 < CAP) g_bkt[(size_t)d.y * CAP + p1] = s.y;
        } else if (i < E) {
            int d = dst[i];
            int p = atomicAdd(&g_count[d], 1);
            if (p < CAP) g_bkt[(size_t)d * CAP + p] = src[i];
        }
    } else {
        int warp = ((blockIdx.x - fillBlocks) * blockDim.x + threadIdx.x) >> 5;
        int lane = threadIdx.x & 31;
        if (warp >= N) return;
        const float4* sv = (const float4*)x;
        float4 a = sv[(size_t)warp * 32 + lane];
        float ss = fmaf(a.x, a.x, fmaf(a.y, a.y, fmaf(a.z, a.z, a.w * a.w)));
        BFLY32(ss);
        float inv = 1.0f / fmaxf(sqrtf(ss), 1e-12f);
        a.x *= inv; a.y *= inv; a.z *= inv; a.w *= inv;
        ((float4*)out)[(size_t)warp * 32 + lane] = a;
        g_h16[0][(size_t)warp * 32 + lane] = f4_to_h4(a);
    }
}

// ---- fused hop: segment-16 gather/gate + noise + normalize -----------------
__global__ void __launch_bounds__(256) k_hop(float* __restrict__ out, int N,
                                             int selin, int selout,
                                             uint32_t nk0, uint32_t nk1) {
    __shared__ float xch[8][128];
    int wslot = threadIdx.x >> 5;
    int node = (blockIdx.x * blockDim.x + threadIdx.x) >> 5;
    int lane = threadIdx.x & 31;
    if (node >= N) return;
    int seg = lane >> 4;       // which edge of the pair this lane works on
    int sl = lane & 15;        // lane within segment; owns dims sl*8..sl*8+7
    const uint4* __restrict__ hv = (const uint4*)g_h16[selin];   // 16 uint4/row

    uint4 hdu = __ldg(&hv[(size_t)node * 16 + sl]);
    __half2 h0 = *(__half2*)&hdu.x, h1 = *(__half2*)&hdu.y;
    __half2 h2 = *(__half2*)&hdu.z, h3 = *(__half2*)&hdu.w;
    float acc[8] = {0.f, 0.f, 0.f, 0.f, 0.f, 0.f, 0.f, 0.f};

    int cnt = min(g_count[node], CAP);
    const int* bkt = g_bkt + (size_t)node * CAP;
    int e = 0;

    // 4 edges per iteration; dA/dB reduced together as packed half2
    for (; e + 4 <= cnt; e += 4) {
        int sA = __ldg(&bkt[e + seg]);
        int sB = __ldg(&bkt[e + 2 + seg]);
        uint4 vA = __ldg(&hv[(size_t)sA * 16 + sl]);
        uint4 vB = __ldg(&hv[(size_t)sB * 16 + sl]);
        float dA = dot8(vA, h0, h1, h2, h3);
        float dB = dot8(vB, h0, h1, h2, h3);
        __half2 dd = __floats2half2_rn(dA, dB);
        #pragma unroll
        for (int off = 8; off >= 1; off >>= 1) {
            uint32_t bits = __shfl_xor_sync(0xffffffffu, *(uint32_t*)&dd, off);
            dd = __hadd2(dd, *(__half2*)&bits);
        }
        float2 df = __half22float2(dd);
        accum8(acc, vA, sigm(df.x));
        accum8(acc, vB, sigm(df.y));
    }
    if (e < cnt) {  // predicated tail quad (1..3 edges left)
        int sA = __ldg(&bkt[min(e + seg, cnt - 1)]);
        int sB = __ldg(&bkt[min(e + 2 + seg, cnt - 1)]);
        uint4 vA = __ldg(&hv[(size_t)sA * 16 + sl]);
        uint4 vB = __ldg(&hv[(size_t)sB * 16 + sl]);
        float dA = dot8(vA, h0, h1, h2, h3);
        float dB = dot8(vB, h0, h1, h2, h3);
        __half2 dd = __floats2half2_rn(dA, dB);
        #pragma unroll
        for (int off = 8; off >= 1; off >>= 1) {
            uint32_t bits = __shfl_xor_sync(0xffffffffu, *(uint32_t*)&dd, off);
            dd = __hadd2(dd, *(__half2*)&bits);
        }
        float2 df = __half22float2(dd);
        float aA = ((e + seg) < cnt) ? sigm(df.x) : 0.f;
        float aB = ((e + 2 + seg) < cnt) ? sigm(df.y) : 0.f;
        accum8(acc, vA, aA);
        accum8(acc, vB, aB);
    }

    // cross-segment sum
    #pragma unroll
    for (int i = 0; i < 8; i++)
        acc[i] += __shfl_xor_sync(0xffffffffu, acc[i], 16);

    // layout exchange: dims sl*8..+7 -> float4 per lane over 32 lanes
    if (seg == 0) {
        #pragma unroll
        for (int i = 0; i < 8; i++) xch[wslot][sl * 8 + i] = acc[i];
    }
    __syncwarp();
    float4 r = ((float4*)xch[wslot])[lane];

    // + SIGMA*normal, l2-normalize, store f32 out + fp16 mirror
    uint32_t base = (uint32_t)node * 128u + (uint32_t)lane * 4u;
    r.x = fmaf(0.1f, tf_normal(nk0, nk1, base + 0u), r.x);
    r.y = fmaf(0.1f, tf_normal(nk0, nk1, base + 1u), r.y);
    r.z = fmaf(0.1f, tf_normal(nk0, nk1, base + 2u), r.z);
    r.w = fmaf(0.1f, tf_normal(nk0, nk1, base + 3u), r.w);
    float ss = fmaf(r.x, r.x, fmaf(r.y, r.y, fmaf(r.z, r.z, r.w * r.w)));
    BFLY32(ss);
    float inv = 1.0f / fmaxf(sqrtf(ss), 1e-12f);
    r.x *= inv; r.y *= inv; r.z *= inv; r.w *= inv;
    ((float4*)out)[(size_t)node * 32 + lane] = r;
    g_h16[selout][(size_t)node * 32 + lane] = f4_to_h4(r);
}

// ---------------------------------------------------------------------------
extern "C" void kernel_launch(void* const* d_in, const int* in_sizes, int n_in,
                              void* d_out, int out_size) {
    const float* x = (const float*)d_in[0];
    const int* ei = (const int*)d_in[1];      // int32 (JAX x64 disabled)
    int N = in_sizes[0] / DIMS;
    int E = in_sizes[1] / 2;
    float* out = (float*)d_out;
    size_t ND = (size_t)N * DIMS;

    uint32_t hk[3][2];
    for (uint32_t i = 0; i < 3; i++) {
        tf2x32(0u, 1u, 0u, i, hk[i][0], hk[i][1]);
    }

    const int* src = ei;
    const int* dst = ei + E;

    int fillBlocks = ((E + 1) / 2 + 255) / 256;
    int nb = (N + 255) / 256;
    int wNodes = (N + 7) / 8;

    // zero counts, then fused [bucket-fill | normalize(x)]
    k_zero<<<nb, 256>>>(N);
    k_front<<<fillBlocks + wNodes, 256>>>(src, dst, E, x, out, N, fillBlocks);

    // 3 fused hops, ping-pong mirrors
    for (int k = 0; k < 3; k++) {
        float* nxt = out + (size_t)(k + 1) * ND;
        k_hop<<<wNodes, 256>>>(nxt, N, k & 1, (k + 1) & 1, hk[k][0], hk[k][1]);
    }
}

// round 12
// speedup vs baseline: 1.0594x; 1.0594x over previous
#include <cuda_runtime.h>
#include <cuda_fp16.h>
#include <cstdint>

// ---------------------------------------------------------------------------
// PMWA_24842090840472: 3-hop gated graph aggregation
// R12: R9 hop kernel verbatim (f32 shfl butterflies — half2 pair-reduce
//      regressed) + R11's fused [bucket-fill | normalize] front kernel.
// ---------------------------------------------------------------------------

#define DIMS 128
#define NMAX 65537
#define CAP 64

__device__ int g_count[NMAX];
__device__ int g_bkt[(size_t)NMAX * CAP];
// fp16 mirrors of h, ping-pong; row = 32 uint2 = 128 halves (dims in order)
__device__ uint2 g_h16[2][(size_t)NMAX * 32];

// ---------------- Threefry-2x32 (JAX key schedule) -------------------------
#define TF_ROUND(x0, x1, r) \
    do { x0 += x1; x1 = ((x1) << (r)) | ((x1) >> (32 - (r))); x1 ^= x0; } while (0)

__host__ __device__ inline void tf2x32(uint32_t k0, uint32_t k1,
                                       uint32_t x0, uint32_t x1,
                                       uint32_t& o0, uint32_t& o1) {
    uint32_t ks0 = k0, ks1 = k1, ks2 = 0x1BD11BDAu ^ k0 ^ k1;
    x0 += ks0; x1 += ks1;
    TF_ROUND(x0, x1, 13); TF_ROUND(x0, x1, 15); TF_ROUND(x0, x1, 26); TF_ROUND(x0, x1, 6);
    x0 += ks1; x1 += ks2 + 1u;
    TF_ROUND(x0, x1, 17); TF_ROUND(x0, x1, 29); TF_ROUND(x0, x1, 16); TF_ROUND(x0, x1, 24);
    x0 += ks2; x1 += ks0 + 2u;
    TF_ROUND(x0, x1, 13); TF_ROUND(x0, x1, 15); TF_ROUND(x0, x1, 26); TF_ROUND(x0, x1, 6);
    x0 += ks0; x1 += ks1 + 3u;
    TF_ROUND(x0, x1, 17); TF_ROUND(x0, x1, 29); TF_ROUND(x0, x1, 16); TF_ROUND(x0, x1, 24);
    x0 += ks1; x1 += ks2 + 4u;
    TF_ROUND(x0, x1, 13); TF_ROUND(x0, x1, 15); TF_ROUND(x0, x1, 26); TF_ROUND(x0, x1, 6);
    x0 += ks2; x1 += ks0 + 5u;
    o0 = x0; o1 = x1;
}

// XLA/Giles float32 erfinv polynomial
__device__ inline float erfinv_xla(float x) {
    float w = -__logf(fmaf(-x, x, 1.0f));
    float p;
    if (w < 5.0f) {
        w -= 2.5f;
        p = 2.81022636e-08f;
        p = fmaf(p, w, 3.43273939e-07f);
        p = fmaf(p, w, -3.5233877e-06f);
        p = fmaf(p, w, -4.39150654e-06f);
        p = fmaf(p, w, 0.00021858087f);
        p = fmaf(p, w, -0.00125372503f);
        p = fmaf(p, w, -0.00417768164f);
        p = fmaf(p, w, 0.246640727f);
        p = fmaf(p, w, 1.50140941f);
    } else {
        w = sqrtf(w) - 3.0f;
        p = -0.000200214257f;
        p = fmaf(p, w, 0.000100950558f);
        p = fmaf(p, w, 0.00134934322f);
        p = fmaf(p, w, -0.00367342844f);
        p = fmaf(p, w, 0.00573950773f);
        p = fmaf(p, w, -0.0076224613f);
        p = fmaf(p, w, 0.00943887047f);
        p = fmaf(p, w, 1.00167406f);
        p = fmaf(p, w, 2.83297682f);
    }
    return p * x;
}

__device__ inline float tf_normal(uint32_t k0, uint32_t k1, uint32_t idx) {
    uint32_t o0, o1;
    tf2x32(k0, k1, 0u, idx, o0, o1);
    uint32_t bits = o0 ^ o1;
    float f = __uint_as_float(0x3f800000u | (bits >> 9)) - 1.0f;
    float u = fmaf(f, 2.0f, -0.99999994f);
    return 1.41421354f * erfinv_xla(u);
}

// ---------------- helpers --------------------------------------------------
#define BFLY32(d)                                       \
    d += __shfl_xor_sync(0xffffffffu, d, 16);           \
    d += __shfl_xor_sync(0xffffffffu, d, 8);            \
    d += __shfl_xor_sync(0xffffffffu, d, 4);            \
    d += __shfl_xor_sync(0xffffffffu, d, 2);            \
    d += __shfl_xor_sync(0xffffffffu, d, 1);

#define SEGRED(d)                                       \
    d += __shfl_xor_sync(0xffffffffu, d, 8);            \
    d += __shfl_xor_sync(0xffffffffu, d, 4);            \
    d += __shfl_xor_sync(0xffffffffu, d, 2);            \
    d += __shfl_xor_sync(0xffffffffu, d, 1);

__device__ __forceinline__ float sigm(float d) {
    return 1.0f / (1.0f + __expf(-d));
}

__device__ __forceinline__ uint2 f4_to_h4(float4 a) {
    __half2 p0 = __floats2half2_rn(a.x, a.y);
    __half2 p1 = __floats2half2_rn(a.z, a.w);
    uint2 u;
    u.x = *(uint32_t*)&p0;
    u.y = *(uint32_t*)&p1;
    return u;
}

// partial dot over this lane's 8 dims (uint4 = 4 half2), fp16 products/f32 tail
__device__ __forceinline__ float dot8(uint4 v, __half2 h0, __half2 h1,
                                      __half2 h2, __half2 h3) {
    __half2 p = __hmul2(*(__half2*)&v.x, h0);
    p = __hfma2(*(__half2*)&v.y, h1, p);
    p = __hfma2(*(__half2*)&v.z, h2, p);
    p = __hfma2(*(__half2*)&v.w, h3, p);
    float2 f = __half22float2(p);
    return f.x + f.y;
}

__device__ __forceinline__ void accum8(float* acc, uint4 v, float a) {
    float2 f0 = __half22float2(*(__half2*)&v.x);
    float2 f1 = __half22float2(*(__half2*)&v.y);
    float2 f2 = __half22float2(*(__half2*)&v.z);
    float2 f3 = __half22float2(*(__half2*)&v.w);
    acc[0] = fmaf(a, f0.x, acc[0]);
    acc[1] = fmaf(a, f0.y, acc[1]);
    acc[2] = fmaf(a, f1.x, acc[2]);
    acc[3] = fmaf(a, f1.y, acc[3]);
    acc[4] = fmaf(a, f2.x, acc[4]);
    acc[5] = fmaf(a, f2.y, acc[5]);
    acc[6] = fmaf(a, f3.x, acc[6]);
    acc[7] = fmaf(a, f3.y, acc[7]);
}

// ---------------- CSR zero -------------------------------------------------
__global__ void k_zero(int N) {
    int i = blockIdx.x * blockDim.x + threadIdx.x;
    if (i < N) g_count[i] = 0;
}

// ------- fused: bucket fill (first fillBlocks) | normalize x (rest) --------
__global__ void k_front(const int* __restrict__ src, const int* __restrict__ dst,
                        int E, const float* __restrict__ x,
                        float* __restrict__ out, int N, int fillBlocks) {
    if ((int)blockIdx.x < fillBlocks) {
        int i = (blockIdx.x * blockDim.x + threadIdx.x) * 2;
        if (i + 1 < E) {
            int2 d = *(const int2*)(dst + i);
            int2 s = *(const int2*)(src + i);
            int p0 = atomicAdd(&g_count[d.x], 1);
            if (p0 < CAP) g_bkt[(size_t)d.x * CAP + p0] = s.x;
            int p1 = atomicAdd(&g_count[d.y], 1);
            if (p1 < CAP) g_bkt[(size_t)d.y * CAP + p1] = s.y;
        } else if (i < E) {
            int d = dst[i];
            int p = atomicAdd(&g_count[d], 1);
            if (p < CAP) g_bkt[(size_t)d * CAP + p] = src[i];
        }
    } else {
        int warp = ((blockIdx.x - fillBlocks) * blockDim.x + threadIdx.x) >> 5;
        int lane = threadIdx.x & 31;
        if (warp >= N) return;
        const float4* sv = (const float4*)x;
        float4 a = sv[(size_t)warp * 32 + lane];
        float ss = fmaf(a.x, a.x, fmaf(a.y, a.y, fmaf(a.z, a.z, a.w * a.w)));
        BFLY32(ss);
        float inv = 1.0f / fmaxf(sqrtf(ss), 1e-12f);
        a.x *= inv; a.y *= inv; a.z *= inv; a.w *= inv;
        ((float4*)out)[(size_t)warp * 32 + lane] = a;
        g_h16[0][(size_t)warp * 32 + lane] = f4_to_h4(a);
    }
}

// ---- fused hop: segment-16 gather/gate + noise + normalize -----------------
__global__ void __launch_bounds__(256) k_hop(float* __restrict__ out, int N,
                                             int selin, int selout,
                                             uint32_t nk0, uint32_t nk1) {
    __shared__ float xch[8][128];
    int wslot = threadIdx.x >> 5;
    int node = (blockIdx.x * blockDim.x + threadIdx.x) >> 5;
    int lane = threadIdx.x & 31;
    if (node >= N) return;
    int seg = lane >> 4;       // which edge of the pair this lane works on
    int sl = lane & 15;        // lane within segment; owns dims sl*8..sl*8+7
    const uint4* __restrict__ hv = (const uint4*)g_h16[selin];   // 16 uint4/row

    uint4 hdu = __ldg(&hv[(size_t)node * 16 + sl]);
    __half2 h0 = *(__half2*)&hdu.x, h1 = *(__half2*)&hdu.y;
    __half2 h2 = *(__half2*)&hdu.z, h3 = *(__half2*)&hdu.w;
    float acc[8] = {0.f, 0.f, 0.f, 0.f, 0.f, 0.f, 0.f, 0.f};

    int cnt = min(g_count[node], CAP);
    const int* bkt = g_bkt + (size_t)node * CAP;
    int e = 0;

    // 4 edges per iteration (2 segment-pairs in flight)
    for (; e + 4 <= cnt; e += 4) {
        int sA = __ldg(&bkt[e + seg]);
        int sB = __ldg(&bkt[e + 2 + seg]);
        uint4 vA = __ldg(&hv[(size_t)sA * 16 + sl]);
        uint4 vB = __ldg(&hv[(size_t)sB * 16 + sl]);
        float dA = dot8(vA, h0, h1, h2, h3);
        float dB = dot8(vB, h0, h1, h2, h3);
        #pragma unroll
        for (int off = 8; off >= 1; off >>= 1) {
            dA += __shfl_xor_sync(0xffffffffu, dA, off);
            dB += __shfl_xor_sync(0xffffffffu, dB, off);
        }
        accum8(acc, vA, sigm(dA));
        accum8(acc, vB, sigm(dB));
    }
    if (e + 2 <= cnt) {
        int sA = __ldg(&bkt[e + seg]);
        uint4 vA = __ldg(&hv[(size_t)sA * 16 + sl]);
        float dA = dot8(vA, h0, h1, h2, h3);
        SEGRED(dA);
        accum8(acc, vA, sigm(dA));
        e += 2;
    }
    if (e < cnt) {
        int s = __ldg(&bkt[e]);               // both segments same edge
        uint4 v = __ldg(&hv[(size_t)s * 16 + sl]);
        float d = dot8(v, h0, h1, h2, h3);
        SEGRED(d);
        float a = (seg == 0) ? sigm(d) : 0.f; // avoid double count
        accum8(acc, v, a);
    }

    // cross-segment sum
    #pragma unroll
    for (int i = 0; i < 8; i++)
        acc[i] += __shfl_xor_sync(0xffffffffu, acc[i], 16);

    // layout exchange: dims sl*8..+7 -> float4 per lane over 32 lanes
    if (seg == 0) {
        #pragma unroll
        for (int i = 0; i < 8; i++) xch[wslot][sl * 8 + i] = acc[i];
    }
    __syncwarp();
    float4 r = ((float4*)xch[wslot])[lane];

    // + SIGMA*normal, l2-normalize, store f32 out + fp16 mirror
    uint32_t base = (uint32_t)node * 128u + (uint32_t)lane * 4u;
    r.x = fmaf(0.1f, tf_normal(nk0, nk1, base + 0u), r.x);
    r.y = fmaf(0.1f, tf_normal(nk0, nk1, base + 1u), r.y);
    r.z = fmaf(0.1f, tf_normal(nk0, nk1, base + 2u), r.z);
    r.w = fmaf(0.1f, tf_normal(nk0, nk1, base + 3u), r.w);
    float ss = fmaf(r.x, r.x, fmaf(r.y, r.y, fmaf(r.z, r.z, r.w * r.w)));
    BFLY32(ss);
    float inv = 1.0f / fmaxf(sqrtf(ss), 1e-12f);
    r.x *= inv; r.y *= inv; r.z *= inv; r.w *= inv;
    ((float4*)out)[(size_t)node * 32 + lane] = r;
    g_h16[selout][(size_t)node * 32 + lane] = f4_to_h4(r);
}

// ---------------------------------------------------------------------------
extern "C" void kernel_launch(void* const* d_in, const int* in_sizes, int n_in,
                              void* d_out, int out_size) {
    const float* x = (const float*)d_in[0];
    const int* ei = (const int*)d_in[1];      // int32 (JAX x64 disabled)
    int N = in_sizes[0] / DIMS;
    int E = in_sizes[1] / 2;
    float* out = (float*)d_out;
    size_t ND = (size_t)N * DIMS;

    uint32_t hk[3][2];
    for (uint32_t i = 0; i < 3; i++) {
        tf2x32(0u, 1u, 0u, i, hk[i][0], hk[i][1]);
    }

    const int* src = ei;
    const int* dst = ei + E;

    int fillBlocks = ((E + 1) / 2 + 255) / 256;
    int nb = (N + 255) / 256;
    int wNodes = (N + 7) / 8;

    // zero counts, then fused [bucket-fill | normalize(x)]
    k_zero<<<nb, 256>>>(N);
    k_front<<<fillBlocks + wNodes, 256>>>(src, dst, E, x, out, N, fillBlocks);

    // 3 fused hops, ping-pong mirrors
    for (int k = 0; k < 3; k++) {
        float* nxt = out + (size_t)(k + 1) * ND;
        k_hop<<<wNodes, 256>>>(nxt, N, k & 1, (k + 1) & 1, hk[k][0], hk[k][1]);
    }
}